// round 2
// baseline (speedup 1.0000x reference)
#include <cuda_runtime.h>
#include <cstdint>

// ---------------------------------------------------------------------------
// MCEwTAAModel: scores[b,n] = <temb[te[b,n]], sum_l w[b,l]*cemb[ev[b,l]]>
// with w[b,l] = softmax_row(taa[ev])[clip(t_c - t_t + R, 0, 2R)]
// taa_bias is a per-row constant -> softmax-invariant -> ignored.
// ---------------------------------------------------------------------------

#define VMAX 50000

// per-row softmax stats: x = row max, y = 1 / sum(exp(v - max))
__device__ float2 g_stats[VMAX];
__device__ int    g_is64;

// --- dtype detection: int64 (high words zero) vs int32 ----------------------
__global__ void detect_kernel(const int* ctx_words) {
    if (threadIdx.x == 0) {
        int is64 = 1;
        #pragma unroll 1
        for (int k = 0; k < 128; k++) {
            if (ctx_words[2 * k + 1] != 0) { is64 = 0; break; }
        }
        g_is64 = is64;
    }
}

// --- pass 1: per-row (max, 1/sumexp) of taa_matrix; one warp per row --------
__global__ void rowstats_kernel(const float* __restrict__ taa, int V, int W) {
    int warp = (blockIdx.x * blockDim.x + threadIdx.x) >> 5;
    int lane = threadIdx.x & 31;
    if (warp >= V) return;
    const float* row = taa + (size_t)warp * W;

    float vals[16];
    int cnt = 0;
    float m = -1e30f;
    for (int j = lane; j < W; j += 32) {
        float v = row[j];
        vals[cnt++] = v;
        m = fmaxf(m, v);
    }
    #pragma unroll
    for (int o = 16; o; o >>= 1) m = fmaxf(m, __shfl_xor_sync(0xffffffffu, m, o));

    float s = 0.f;
    for (int i = 0; i < cnt; i++) s += __expf(vals[i] - m);
    #pragma unroll
    for (int o = 16; o; o >>= 1) s += __shfl_xor_sync(0xffffffffu, s, o);

    if (lane == 0) g_stats[warp] = make_float2(m, 1.0f / s);
}

// --- pass 2+3 fused: one CTA per batch row, 256 threads (= E) ---------------
__device__ __forceinline__ long long load_idx(const void* p, long long i, int is64) {
    if (is64) return ((const long long*)p)[i];
    return (long long)((const int*)p)[i];
}

__global__ __launch_bounds__(256, 8)
void main_kernel(const void* __restrict__ ctx_v,
                 const void* __restrict__ tgt_v,
                 const float* __restrict__ cemb,
                 const float* __restrict__ temb,
                 const float* __restrict__ taa,
                 float* __restrict__ out,
                 int L, int NOPT, int W) {
    __shared__ float w_sh[256];
    __shared__ int   off_sh[256];
    __shared__ float h_sh[256];

    const int b = blockIdx.x;
    const int t = threadIdx.x;
    const int is64 = g_is64;
    const int R = (W - 1) / 2;

    // Phase A: weights for each context position
    if (t < L) {
        long long ci = ((long long)b * L + t) * 2;
        long long ev = load_idx(ctx_v, ci, is64);
        long long tm = load_idx(ctx_v, ci + 1, is64);
        long long tt = load_idx(tgt_v, (long long)b * (NOPT + 1) + NOPT, is64);

        float mask = 1.0f;
        if (ev == -1) { mask = 0.0f; ev = 0; }

        long long d = tm - tt + R;
        if (d < 0) d = 0;
        if (d > 2 * R) d = 2 * R;

        float2 st = g_stats[ev];
        float x = taa[(size_t)ev * W + (int)d];
        w_sh[t] = mask * __expf(x - st.x) * st.y;
        off_sh[t] = (int)ev * 256;
    }
    __syncthreads();

    // Phase B: hidden[e] accumulation, fully coalesced gathers over L2-resident table
    float h = 0.f;
    const float* ce = cemb + t;
    #pragma unroll 8
    for (int l = 0; l < L; l++) {
        h = fmaf(w_sh[l], __ldg(ce + off_sh[l]), h);
    }
    h_sh[t] = h;
    __syncthreads();

    // Phase C: scores for NOPT targets, one warp per target (round-robin)
    const int wid = t >> 5, lane = t & 31;
    for (int n = wid; n < NOPT; n += 8) {
        long long te = load_idx(tgt_v, (long long)b * (NOPT + 1) + n, is64);
        const float* tr = temb + (size_t)te * 256;
        float s = 0.f;
        #pragma unroll
        for (int e = lane; e < 256; e += 32) s = fmaf(tr[e], h_sh[e], s);
        #pragma unroll
        for (int o = 16; o; o >>= 1) s += __shfl_xor_sync(0xffffffffu, s, o);
        if (lane == 0) out[b * NOPT + n] = s;
    }
}

// ---------------------------------------------------------------------------
extern "C" void kernel_launch(void* const* d_in, const int* in_sizes, int n_in,
                              void* d_out, int out_size) {
    const void*  ctx  = d_in[0];           // context       (B, L, 2)  int
    const void*  tgt  = d_in[1];           // mixed_target  (B, NOPT+1) int
    const float* cemb = (const float*)d_in[2]; // (V, E)
    const float* temb = (const float*)d_in[3]; // (V, E)
    const float* taa  = (const float*)d_in[4]; // (V, W)
    // d_in[5] = taa_bias: softmax-invariant, skipped.
    float* out = (float*)d_out;

    const int V    = in_sizes[5];
    const int W    = in_sizes[4] / V;                 // 2R+1 = 361
    const int B    = in_sizes[1] - out_size;          // B(N+1) - BN
    const int NOPT = out_size / B;
    const int L    = in_sizes[0] / (2 * B);

    detect_kernel<<<1, 32>>>((const int*)ctx);

    int rows_per_block = 256 / 32;                    // 8 warps/block
    int nblk = (V + rows_per_block - 1) / rows_per_block;
    rowstats_kernel<<<nblk, 256>>>(taa, V, W);

    main_kernel<<<B, 256>>>(ctx, tgt, cemb, temb, taa, out, L, NOPT, W);
}

// round 3
// speedup vs baseline: 1.1989x; 1.1989x over previous
#include <cuda_runtime.h>
#include <cstdint>

// ---------------------------------------------------------------------------
// MCEwTAAModel: scores[b,n] = <temb[te[b,n]], sum_l w[b,l]*cemb[ev[b,l]]>
// with w[b,l] = softmax_row(taa[ev])[clip(t_c - t_t + R, 0, 2R)]
// taa_bias is a per-row constant -> softmax-invariant -> ignored.
// ---------------------------------------------------------------------------

#define VMAX 50000

// per-row softmax stats: x = row max, y = 1 / sum(exp(v - max))
__device__ float2 g_stats[VMAX];
__device__ int    g_is64;

// --- dtype detection: int64 (high words zero) vs int32, parallel ------------
__global__ void detect_kernel(const int* ctx_words) {
    int odd = ctx_words[2 * threadIdx.x + 1];
    int all_zero = __syncthreads_and(odd == 0);
    if (threadIdx.x == 0) g_is64 = all_zero;
}

// --- pass 1: per-row (max, 1/sumexp) of taa_matrix; one warp per row --------
// __ldcs: evict-first streaming so the 72MB taa scan doesn't flush the
// L2-resident cemb table between graph replays.
__global__ void rowstats_kernel(const float* __restrict__ taa, int V, int W) {
    int warp = (blockIdx.x * blockDim.x + threadIdx.x) >> 5;
    int lane = threadIdx.x & 31;
    if (warp >= V) return;
    const float* row = taa + (size_t)warp * W;

    float vals[16];
    int cnt = 0;
    float m = -1e30f;
    for (int j = lane; j < W; j += 32) {
        float v = __ldcs(row + j);
        vals[cnt++] = v;
        m = fmaxf(m, v);
    }
    #pragma unroll
    for (int o = 16; o; o >>= 1) m = fmaxf(m, __shfl_xor_sync(0xffffffffu, m, o));

    float s = 0.f;
    for (int i = 0; i < cnt; i++) s += __expf(vals[i] - m);
    #pragma unroll
    for (int o = 16; o; o >>= 1) s += __shfl_xor_sync(0xffffffffu, s, o);

    if (lane == 0) g_stats[warp] = make_float2(m, 1.0f / s);
}

// --- pass 2+3 fused: one CTA per batch row, 256 threads ---------------------
__device__ __forceinline__ long long load_idx(const void* p, long long i, int is64) {
    if (is64) return ((const long long*)p)[i];
    return (long long)((const int*)p)[i];
}

__global__ __launch_bounds__(256, 8)
void main_kernel(const void* __restrict__ ctx_v,
                 const void* __restrict__ tgt_v,
                 const float* __restrict__ cemb,
                 const float* __restrict__ temb,
                 const float* __restrict__ taa,
                 float* __restrict__ out,
                 int L, int NOPT, int W) {
    __shared__ float  w_sh[256];
    __shared__ int    off_sh[256];
    __shared__ float4 part4[4][64];   // per-group partial hidden
    __shared__ float  h_sh[256];

    const int b = blockIdx.x;
    const int t = threadIdx.x;
    const int is64 = g_is64;
    const int R = (W - 1) / 2;

    // Phase A: weights for each context position (zero-pad to 256)
    if (t < L) {
        long long ci = ((long long)b * L + t) * 2;
        long long ev = load_idx(ctx_v, ci, is64);
        long long tm = load_idx(ctx_v, ci + 1, is64);
        long long tt = load_idx(tgt_v, (long long)b * (NOPT + 1) + NOPT, is64);

        float mask = 1.0f;
        if (ev == -1) { mask = 0.0f; ev = 0; }

        long long d = tm - tt + R;
        if (d < 0) d = 0;
        if (d > 2 * R) d = 2 * R;

        float2 st = g_stats[ev];
        float x = taa[(size_t)ev * W + (int)d];
        w_sh[t]   = mask * __expf(x - st.x) * st.y;
        off_sh[t] = (int)ev * 64;      // row offset in float4 units (E=256)
    } else {
        w_sh[t]   = 0.0f;
        off_sh[t] = 0;
    }
    __syncthreads();

    // Phase B: hidden accumulation. 4 event-groups in flight; each group of
    // 64 threads covers a full 256-channel row with float4 (LDG.128) loads.
    const int g = t >> 6;              // group 0..3 (constant within a warp)
    const int q = t & 63;              // float4 lane within row
    const int Lpad = (L + 3) & ~3;
    const float4* cemb4 = (const float4*)cemb;

    float4 acc = make_float4(0.f, 0.f, 0.f, 0.f);
    #pragma unroll 4
    for (int l0 = 0; l0 < Lpad; l0 += 4) {
        int   l = l0 + g;
        float w = w_sh[l];
        float4 v = __ldg(cemb4 + off_sh[l] + q);
        acc.x = fmaf(w, v.x, acc.x);
        acc.y = fmaf(w, v.y, acc.y);
        acc.z = fmaf(w, v.z, acc.z);
        acc.w = fmaf(w, v.w, acc.w);
    }
    part4[g][q] = acc;
    __syncthreads();

    // reduce 4 groups -> h_sh[256]
    {
        const float* p = (const float*)part4;
        h_sh[t] = p[t] + p[256 + t] + p[512 + t] + p[768 + t];
    }
    __syncthreads();

    // Phase C: scores for NOPT targets, one warp per target (round-robin)
    const int wid = t >> 5, lane = t & 31;
    const float4* h4 = (const float4*)h_sh;
    for (int n = wid; n < NOPT; n += 8) {
        long long te = load_idx(tgt_v, (long long)b * (NOPT + 1) + n, is64);
        const float4* tr = (const float4*)(temb + (size_t)te * 256);
        float s = 0.f;
        #pragma unroll
        for (int e = lane; e < 64; e += 32) {
            float4 a = __ldg(tr + e);
            float4 hh = h4[e];
            s = fmaf(a.x, hh.x, s);
            s = fmaf(a.y, hh.y, s);
            s = fmaf(a.z, hh.z, s);
            s = fmaf(a.w, hh.w, s);
        }
        #pragma unroll
        for (int o = 16; o; o >>= 1) s += __shfl_xor_sync(0xffffffffu, s, o);
        if (lane == 0) out[b * NOPT + n] = s;
    }
}

// ---------------------------------------------------------------------------
extern "C" void kernel_launch(void* const* d_in, const int* in_sizes, int n_in,
                              void* d_out, int out_size) {
    const void*  ctx  = d_in[0];               // context       (B, L, 2)  int
    const void*  tgt  = d_in[1];               // mixed_target  (B, NOPT+1) int
    const float* cemb = (const float*)d_in[2]; // (V, E)
    const float* temb = (const float*)d_in[3]; // (V, E)
    const float* taa  = (const float*)d_in[4]; // (V, W)
    // d_in[5] = taa_bias: softmax-invariant, skipped.
    float* out = (float*)d_out;

    const int V    = in_sizes[5];
    const int W    = in_sizes[4] / V;                 // 2R+1 = 361
    const int B    = in_sizes[1] - out_size;          // B(N+1) - BN
    const int NOPT = out_size / B;
    const int L    = in_sizes[0] / (2 * B);

    detect_kernel<<<1, 128>>>((const int*)ctx);

    int rows_per_block = 256 / 32;                    // 8 warps/block
    int nblk = (V + rows_per_block - 1) / rows_per_block;
    rowstats_kernel<<<nblk, 256>>>(taa, V, W);

    main_kernel<<<B, 256>>>(ctx, tgt, cemb, temb, taa, out, L, NOPT, W);
}

// round 4
// speedup vs baseline: 1.2352x; 1.0303x over previous
#include <cuda_runtime.h>
#include <cstdint>

// ---------------------------------------------------------------------------
// MCEwTAAModel: scores[b,n] = <temb[te[b,n]], sum_l w[b,l]*cemb[ev[b,l]]>
// with w[b,l] = softmax_row(taa[ev])[clip(t_c - t_t + R, 0, 2R)]
// taa_bias is a per-row constant -> softmax-invariant -> ignored.
// ---------------------------------------------------------------------------

#define VMAX 50000

// per-row softmax stats: x = row max, y = 1 / sum(exp(v - max))
__device__ float2 g_stats[VMAX];
__device__ int    g_is64;

// --- pass 1: per-row (max, 1/sumexp) of taa_matrix; one warp per row --------
// Block 0 additionally runs the int64-vs-int32 dtype detection (high words of
// non-negative int64 are all zero), replacing the former separate kernel.
// __ldcs: evict-first streaming so the 72MB taa scan doesn't flush the
// L2-resident cemb table between graph replays.
__global__ void rowstats_kernel(const float* __restrict__ taa,
                                const int* __restrict__ ctx_words,
                                int V, int W) {
    if (blockIdx.x == 0) {
        int t = threadIdx.x;
        int ok = 1;
        if (t < 128) ok = (ctx_words[2 * t + 1] == 0);
        int all = __syncthreads_and(ok);
        if (t == 0) g_is64 = all;
    }

    int warp = (blockIdx.x * blockDim.x + threadIdx.x) >> 5;
    int lane = threadIdx.x & 31;
    if (warp >= V) return;
    const float* row = taa + (size_t)warp * W;

    float vals[16];
    int cnt = 0;
    float m = -1e30f;
    for (int j = lane; j < W; j += 32) {
        float v = __ldcs(row + j);
        vals[cnt++] = v;
        m = fmaxf(m, v);
    }
    #pragma unroll
    for (int o = 16; o; o >>= 1) m = fmaxf(m, __shfl_xor_sync(0xffffffffu, m, o));

    float s = 0.f;
    for (int i = 0; i < cnt; i++) s += __expf(vals[i] - m);
    #pragma unroll
    for (int o = 16; o; o >>= 1) s += __shfl_xor_sync(0xffffffffu, s, o);

    if (lane == 0) g_stats[warp] = make_float2(m, 1.0f / s);
}

// --- pass 2+3 fused: one CTA per batch row, 256 threads ---------------------
__device__ __forceinline__ long long load_idx(const void* p, long long i, int is64) {
    if (is64) return ((const long long*)p)[i];
    return (long long)((const int*)p)[i];
}

__global__ __launch_bounds__(256, 8)
void main_kernel(const void* __restrict__ ctx_v,
                 const void* __restrict__ tgt_v,
                 const float* __restrict__ cemb,
                 const float* __restrict__ temb,
                 const float* __restrict__ taa,
                 float* __restrict__ out,
                 int L, int NOPT, int W) {
    __shared__ float2 wo_sh[256];     // .x = weight, .y = row offset (int bits)
    __shared__ float4 part4[4][64];   // per-group partial hidden
    __shared__ float  h_sh[256];

    const int b = blockIdx.x;
    const int t = threadIdx.x;
    const int is64 = g_is64;
    const int R = (W - 1) / 2;

    // Phase A: weights for each context position (zero-pad to 256)
    if (t < L) {
        long long ci = ((long long)b * L + t) * 2;
        long long ev = load_idx(ctx_v, ci, is64);
        long long tm = load_idx(ctx_v, ci + 1, is64);
        long long tt = load_idx(tgt_v, (long long)b * (NOPT + 1) + NOPT, is64);

        float mask = 1.0f;
        if (ev == -1) { mask = 0.0f; ev = 0; }

        long long d = tm - tt + R;
        if (d < 0) d = 0;
        if (d > 2 * R) d = 2 * R;

        float2 st = g_stats[ev];
        float x = taa[(size_t)ev * W + (int)d];
        float w = mask * __expf(x - st.x) * st.y;
        wo_sh[t] = make_float2(w, __int_as_float((int)ev * 64));
    } else {
        wo_sh[t] = make_float2(0.0f, __int_as_float(0));
    }
    __syncthreads();

    // Phase B: hidden accumulation. 4 event-groups in flight; each group of
    // 64 threads covers a full 256-channel row with float4 (LDG.128) loads.
    const int g = t >> 6;              // group 0..3 (constant within a warp)
    const int q = t & 63;              // float4 lane within row
    const int Lpad = (L + 3) & ~3;
    const float4* cemb4 = (const float4*)cemb;

    float4 acc = make_float4(0.f, 0.f, 0.f, 0.f);
    #pragma unroll 4
    for (int l0 = 0; l0 < Lpad; l0 += 4) {
        float2 wo = wo_sh[l0 + g];               // broadcast LDS.64
        float4 v  = __ldg(cemb4 + __float_as_int(wo.y) + q);
        acc.x = fmaf(wo.x, v.x, acc.x);
        acc.y = fmaf(wo.x, v.y, acc.y);
        acc.z = fmaf(wo.x, v.z, acc.z);
        acc.w = fmaf(wo.x, v.w, acc.w);
    }
    part4[g][q] = acc;
    __syncthreads();

    // reduce 4 groups -> h_sh[256]
    {
        const float* p = (const float*)part4;
        h_sh[t] = (p[t] + p[256 + t]) + (p[512 + t] + p[768 + t]);
    }
    __syncthreads();

    // Phase C: scores for NOPT targets, one warp per target (round-robin)
    const int wid = t >> 5, lane = t & 31;
    const float4* h4 = (const float4*)h_sh;
    for (int n = wid; n < NOPT; n += 8) {
        long long te = load_idx(tgt_v, (long long)b * (NOPT + 1) + n, is64);
        const float4* tr = (const float4*)(temb + (size_t)te * 256);
        float s = 0.f;
        #pragma unroll
        for (int e = lane; e < 64; e += 32) {
            float4 a = __ldg(tr + e);
            float4 hh = h4[e];
            s = fmaf(a.x, hh.x, s);
            s = fmaf(a.y, hh.y, s);
            s = fmaf(a.z, hh.z, s);
            s = fmaf(a.w, hh.w, s);
        }
        #pragma unroll
        for (int o = 16; o; o >>= 1) s += __shfl_xor_sync(0xffffffffu, s, o);
        if (lane == 0) out[b * NOPT + n] = s;
    }
}

// ---------------------------------------------------------------------------
extern "C" void kernel_launch(void* const* d_in, const int* in_sizes, int n_in,
                              void* d_out, int out_size) {
    const void*  ctx  = d_in[0];               // context       (B, L, 2)  int
    const void*  tgt  = d_in[1];               // mixed_target  (B, NOPT+1) int
    const float* cemb = (const float*)d_in[2]; // (V, E)
    const float* temb = (const float*)d_in[3]; // (V, E)
    const float* taa  = (const float*)d_in[4]; // (V, W)
    // d_in[5] = taa_bias: softmax-invariant, skipped.
    float* out = (float*)d_out;

    const int V    = in_sizes[5];
    const int W    = in_sizes[4] / V;                 // 2R+1 = 361
    const int B    = in_sizes[1] - out_size;          // B(N+1) - BN
    const int NOPT = out_size / B;
    const int L    = in_sizes[0] / (2 * B);

    int rows_per_block = 256 / 32;                    // 8 warps/block
    int nblk = (V + rows_per_block - 1) / rows_per_block;
    rowstats_kernel<<<nblk, 256>>>(taa, (const int*)ctx, V, W);

    main_kernel<<<B, 256>>>(ctx, tgt, cemb, temb, taa, out, L, NOPT, W);
}

// round 5
// speedup vs baseline: 1.4936x; 1.2091x over previous
#include <cuda_runtime.h>
#include <cuda_fp16.h>
#include <cstdint>

// ---------------------------------------------------------------------------
// MCEwTAAModel: scores[b,n] = <temb[te[b,n]], sum_l w[b,l]*cemb[ev[b,l]]>
// with w[b,l] = softmax_row(taa[ev])[clip(t_c - t_t + R, 0, 2R)]
// taa_bias is a per-row constant -> softmax-invariant -> ignored.
// Gathers run against an fp16 copy of cemb (rebuilt every call) to halve
// the dominant L2 gather traffic. Accumulation stays fp32.
// ---------------------------------------------------------------------------

#define VMAX 50000
#define EDIM 256

// per-row softmax stats: x = row max, y = 1 / sum(exp(v - max))
__device__ float2  g_stats[VMAX];
__device__ int     g_is64;
__device__ __half2 g_cemb_h[VMAX * (EDIM / 2)];   // 25.6 MB fp16 gather table

// --- pass 1 (fused): dtype detect + rowstats + cemb->fp16 conversion --------
// Blocks [0, nblk_stats): one warp per taa row -> (max, 1/sumexp).
// Blocks [nblk_stats, grid): grid-stride convert of cemb to fp16.
// __ldcs on both streams: evict-first, don't flush L2 between replays.
__global__ void pass1_kernel(const float* __restrict__ taa,
                             const int*   __restrict__ ctx_words,
                             const float4* __restrict__ cemb4,
                             int V, int W, int nblk_stats) {
    if (blockIdx.x < nblk_stats) {
        // dtype detection (block 0 only): int64 indices have zero high words
        if (blockIdx.x == 0) {
            int t = threadIdx.x;
            int ok = (t < 128) ? (ctx_words[2 * t + 1] == 0) : 1;
            int all = __syncthreads_and(ok);
            if (t == 0) g_is64 = all;
        }

        int row_id = (blockIdx.x * blockDim.x + threadIdx.x) >> 5;
        int lane   = threadIdx.x & 31;
        if (row_id >= V) return;
        const float* row = taa + (size_t)row_id * W;

        // fixed register array, fully unrolled -> no local-memory spill
        float vals[12];
        float m = -1e30f;
        #pragma unroll
        for (int i = 0; i < 12; i++) {
            int j = lane + i * 32;
            float v = (j < W) ? __ldcs(row + j) : -1e30f;
            vals[i] = v;
            m = fmaxf(m, v);
        }
        // rare fallback for W > 384 (not hit for W=361)
        for (int j = lane + 384; j < W; j += 32) m = fmaxf(m, __ldcs(row + j));

        #pragma unroll
        for (int o = 16; o; o >>= 1) m = fmaxf(m, __shfl_xor_sync(0xffffffffu, m, o));

        float s = 0.f;
        #pragma unroll
        for (int i = 0; i < 12; i++) s += __expf(vals[i] - m);
        for (int j = lane + 384; j < W; j += 32) s += __expf(__ldcs(row + j) - m);
        #pragma unroll
        for (int o = 16; o; o >>= 1) s += __shfl_xor_sync(0xffffffffu, s, o);

        if (lane == 0) g_stats[row_id] = make_float2(m, 1.0f / s);
    } else {
        // cemb fp32 -> fp16 conversion, grid-stride over float4 elements
        int cb    = blockIdx.x - nblk_stats;
        int nconv = gridDim.x - nblk_stats;
        int N4    = V * (EDIM / 4);
        for (int i = cb * blockDim.x + threadIdx.x; i < N4;
             i += nconv * blockDim.x) {
            float4 v = __ldcs(cemb4 + i);
            g_cemb_h[2 * i]     = __floats2half2_rn(v.x, v.y);
            g_cemb_h[2 * i + 1] = __floats2half2_rn(v.z, v.w);
        }
    }
}

// --- pass 2+3 fused: one CTA per batch row, 256 threads ---------------------
__device__ __forceinline__ long long load_idx(const void* p, long long i, int is64) {
    if (is64) return ((const long long*)p)[i];
    return (long long)((const int*)p)[i];
}

__global__ __launch_bounds__(256, 6)
void main_kernel(const void* __restrict__ ctx_v,
                 const void* __restrict__ tgt_v,
                 const float* __restrict__ temb,
                 const float* __restrict__ taa,
                 float* __restrict__ out,
                 int L, int NOPT, int W) {
    __shared__ float2 wo_sh[256];     // .x = weight, .y = row offset (int bits)
    __shared__ float4 part4[4][64];   // per-group partial hidden
    __shared__ float  h_sh[256];

    const int b = blockIdx.x;
    const int t = threadIdx.x;
    const int is64 = g_is64;
    const int R = (W - 1) / 2;

    // Phase A: weights for each context position (zero-pad to 256)
    if (t < L) {
        long long ci = ((long long)b * L + t) * 2;
        long long ev = load_idx(ctx_v, ci, is64);
        long long tm = load_idx(ctx_v, ci + 1, is64);
        long long tt = load_idx(tgt_v, (long long)b * (NOPT + 1) + NOPT, is64);

        float mask = 1.0f;
        if (ev == -1) { mask = 0.0f; ev = 0; }

        long long d = tm - tt + R;
        if (d < 0) d = 0;
        if (d > 2 * R) d = 2 * R;

        float2 st = g_stats[ev];
        float x = taa[(size_t)ev * W + (int)d];
        float w = mask * __expf(x - st.x) * st.y;
        wo_sh[t] = make_float2(w, __int_as_float((int)ev * 64));
    } else {
        wo_sh[t] = make_float2(0.0f, __int_as_float(0));
    }
    __syncthreads();

    // Phase B: hidden accumulation over fp16 table. 4 event-groups in flight;
    // each group of 64 threads covers a 256-channel row with uint2 (4xfp16).
    const int g = t >> 6;              // group 0..3 (constant within a warp)
    const int q = t & 63;              // uint2 lane within row
    const int Lpad = (L + 3) & ~3;
    const uint2* ch2 = (const uint2*)g_cemb_h;

    float4 acc = make_float4(0.f, 0.f, 0.f, 0.f);
    #pragma unroll 4
    for (int l0 = 0; l0 < Lpad; l0 += 4) {
        float2 wo = wo_sh[l0 + g];               // broadcast LDS.64
        float  w  = wo.x;
        uint2  u  = __ldg(ch2 + __float_as_int(wo.y) + q);
        float2 f0 = __half22float2(*(const __half2*)&u.x);
        float2 f1 = __half22float2(*(const __half2*)&u.y);
        acc.x = fmaf(w, f0.x, acc.x);
        acc.y = fmaf(w, f0.y, acc.y);
        acc.z = fmaf(w, f1.x, acc.z);
        acc.w = fmaf(w, f1.y, acc.w);
    }
    part4[g][q] = acc;
    __syncthreads();

    // reduce 4 groups -> h_sh[256]
    {
        const float* p = (const float*)part4;
        h_sh[t] = (p[t] + p[256 + t]) + (p[512 + t] + p[768 + t]);
    }
    __syncthreads();

    // Phase C: scores for NOPT targets, one warp per target (round-robin)
    const int wid = t >> 5, lane = t & 31;
    const float4* h4 = (const float4*)h_sh;
    for (int n = wid; n < NOPT; n += 8) {
        long long te = load_idx(tgt_v, (long long)b * (NOPT + 1) + n, is64);
        const float4* tr = (const float4*)(temb + (size_t)te * 256);
        float s = 0.f;
        #pragma unroll
        for (int e = lane; e < 64; e += 32) {
            float4 a = __ldg(tr + e);
            float4 hh = h4[e];
            s = fmaf(a.x, hh.x, s);
            s = fmaf(a.y, hh.y, s);
            s = fmaf(a.z, hh.z, s);
            s = fmaf(a.w, hh.w, s);
        }
        #pragma unroll
        for (int o = 16; o; o >>= 1) s += __shfl_xor_sync(0xffffffffu, s, o);
        if (lane == 0) out[b * NOPT + n] = s;
    }
}

// ---------------------------------------------------------------------------
extern "C" void kernel_launch(void* const* d_in, const int* in_sizes, int n_in,
                              void* d_out, int out_size) {
    const void*  ctx  = d_in[0];               // context       (B, L, 2)  int
    const void*  tgt  = d_in[1];               // mixed_target  (B, NOPT+1) int
    const float* cemb = (const float*)d_in[2]; // (V, E)
    const float* temb = (const float*)d_in[3]; // (V, E)
    const float* taa  = (const float*)d_in[4]; // (V, W)
    // d_in[5] = taa_bias: softmax-invariant, skipped.
    float* out = (float*)d_out;

    const int V    = in_sizes[5];
    const int W    = in_sizes[4] / V;                 // 2R+1 = 361
    const int B    = in_sizes[1] - out_size;          // B(N+1) - BN
    const int NOPT = out_size / B;
    const int L    = in_sizes[0] / (2 * B);

    const int rows_per_block = 256 / 32;              // 8 warps/block
    const int nblk_stats = (V + rows_per_block - 1) / rows_per_block;
    const int nblk_conv  = (V * (EDIM / 4) + 255) / 256;  // 1 float4/thread
    pass1_kernel<<<nblk_stats + nblk_conv, 256>>>(
        taa, (const int*)ctx, (const float4*)cemb, V, W, nblk_stats);

    main_kernel<<<B, 256>>>(ctx, tgt, temb, taa, out, L, NOPT, W);
}